// round 13
// baseline (speedup 1.0000x reference)
#include <cuda_runtime.h>
#include <cuda_fp16.h>
#include <cstdint>
#include <math.h>

typedef unsigned long long ull;

#define FMA2(acc, a, b) asm("fma.rn.f32x2 %0, %1, %2, %0;" : "+l"(acc) : "l"(a), "l"(b))
#define PACK2(d, s)     asm("mov.b64 %0, {%1, %1};" : "=l"(d) : "f"(s))
#define UNPACK2(lo, hi, s) asm("mov.b64 {%0, %1}, %2;" : "=f"(lo), "=f"(hi) : "l"(s))

constexpr int N    = 8192;
constexpr int FIN  = 512;
constexpr int FOUT = 128;
constexpr int NQ   = 512;    // k16 chunks

__device__ float g_h[N * FOUT];
__device__ uint2 g_hTb[NQ * 16 * 4 * 8];     // fp16 B fragments of h^T (2MB, L2-resident)
__device__ float g_E1[N], g_F1[N], g_E2[N], g_F2[N];

__device__ __forceinline__ uint32_t pack_h2(float lo, float hi) {
    uint32_t r;
    asm("cvt.rn.f16x2.f32 %0, %1, %2;" : "=r"(r) : "f"(hi), "f"(lo));
    return r;
}

// m16n8k16 fp16 warp MMA, fp32 accumulate
__device__ __forceinline__ void mma16(float* c, uint32_t a0, uint32_t a1, uint32_t a2,
                                      uint32_t a3, uint32_t b0, uint32_t b1) {
    asm volatile(
        "mma.sync.aligned.m16n8k16.row.col.f32.f16.f16.f32 "
        "{%0,%1,%2,%3}, {%4,%5,%6,%7}, {%8,%9}, {%0,%1,%2,%3};"
        : "+f"(c[0]), "+f"(c[1]), "+f"(c[2]), "+f"(c[3])
        : "r"(a0), "r"(a1), "r"(a2), "r"(a3), "r"(b0), "r"(b1));
}

__device__ __forceinline__ float elu_f(float v) { return v > 0.f ? v : expm1f(v); }

// ---------------------------------------------------------------------------
// Kernel A: h = X @ W (fp32 FFMA2), BM=64, 512 threads (2 col-halves of 64).
// Emits g_h and fp16 B-fragment hT.
// ---------------------------------------------------------------------------
__global__ void __launch_bounds__(512) k_gemm_hw(const float* __restrict__ X,
                                                 const float* __restrict__ W) {
    __shared__ float sX[64][32];    // 8KB
    __shared__ float sB[32][FOUT];  // 16KB
    const int t = threadIdx.x;
    const int g  = t >> 8;          // col half: cols [64g, 64g+64)
    const int u  = t & 255;
    const int tx = u & 15;          // 4 cols: c0 = 64g + 4tx
    const int ty = u >> 4;          // rows ty + 16k, k<4
    const int m0 = blockIdx.x * 64;
    const int xr = t >> 3, xc0 = (t & 7) * 4;
    const int wr = t >> 4, wc0 = (t & 15) * 8;

    ull acc[4][2] = {};
    for (int kc = 0; kc < FIN / 32; ++kc) {
        const int k0 = kc * 32;
        __syncthreads();
        {
            float4*       dx = reinterpret_cast<float4*>(&sX[xr][xc0]);
            const float4* sx = reinterpret_cast<const float4*>(X + (size_t)(m0 + xr) * FIN + k0 + xc0);
            dx[0] = sx[0];
            float4*       dw = reinterpret_cast<float4*>(&sB[wr][wc0]);
            const float4* sw = reinterpret_cast<const float4*>(W + (size_t)(k0 + wr) * FOUT + wc0);
            dw[0] = sw[0]; dw[1] = sw[1];
        }
        __syncthreads();
        #pragma unroll 8
        for (int kk = 0; kk < 32; ++kk) {
            ulonglong2 b2 = *reinterpret_cast<const ulonglong2*>(&sB[kk][g * 64 + tx * 4]);
            #pragma unroll
            for (int k = 0; k < 4; ++k) {
                ull ap; PACK2(ap, sX[ty + 16 * k][kk]);
                FMA2(acc[k][0], ap, b2.x);
                FMA2(acc[k][1], ap, b2.y);
            }
        }
    }
    __half* hTb = reinterpret_cast<__half*>(g_hTb);
    #pragma unroll
    for (int k = 0; k < 4; ++k) {
        const int r = m0 + ty + 16 * k;
        float4 o;
        UNPACK2(o.x, o.y, acc[k][0]);
        UNPACK2(o.z, o.w, acc[k][1]);
        reinterpret_cast<float4*>(g_h + (size_t)r * FOUT)[g * 16 + tx] = o;
        const int q   = r >> 4;
        const int lcr = (r >> 2) & 3;
        const int p   = r & 3;
        const float v[4] = {o.x, o.y, o.z, o.w};
        #pragma unroll
        for (int c = 0; c < 4; ++c) {
            const int f = g * 64 + tx * 4 + c;
            const int idx = (((q * 16 + (f >> 3)) * 4 + lcr) * 8 + (f & 7)) * 4 + p;
            hTb[idx] = __float2half_rn(v[c]);
        }
    }
}

// ---------------------------------------------------------------------------
// Kernel B: E/F exp vectors
// ---------------------------------------------------------------------------
__global__ void __launch_bounds__(128) k_scores(const float* __restrict__ a) {
    const int i = blockIdx.x;
    const int t = threadIdx.x;
    const float hv = g_h[(size_t)i * FOUT + t];
    float p1 = hv * __ldg(&a[t]);
    float p2 = hv * __ldg(&a[FOUT + t]);
    #pragma unroll
    for (int off = 16; off; off >>= 1) {
        p1 += __shfl_xor_sync(0xffffffffu, p1, off);
        p2 += __shfl_xor_sync(0xffffffffu, p2, off);
    }
    __shared__ float r1[4], r2[4];
    const int w = t >> 5;
    if ((t & 31) == 0) { r1[w] = p1; r2[w] = p2; }
    __syncthreads();
    if (t == 0) {
        const float s1 = r1[0] + r1[1] + r1[2] + r1[3];
        const float s2 = r2[0] + r2[1] + r2[2] + r2[3];
        g_E1[i] = __expf(s1);  g_F1[i] = __expf(0.2f * s1);
        g_E2[i] = __expf(s2);  g_F2[i] = __expf(0.2f * s2);
    }
}

// ---------------------------------------------------------------------------
// Kernel C: fp16 warp-MMA aggregation, 24 warps (768 thr), 3-way j-split.
// Warp-group g (8 warps): chunks [qs[g], qs[g+1]); 6 warps/SMSP in flight.
// No mainloop syncs; groups 1,2 export accumulators via smem; group 0 merges.
// den from fp32 weights on w8==1 (rows 0-31) and w8==6 (rows 32-63) per group
// (rounding mismatch ~1e-5, negligible).
// ---------------------------------------------------------------------------
__global__ void __launch_bounds__(768, 1) k_agg(const int* __restrict__ adj,
                                                float* __restrict__ out) {
    extern __shared__ float smem[];
    float* sEF    = smem;                   // 16384 f (64KB): E2 | F2
    float* sMerge = smem + 2 * N;           // 16384 f (64KB): group-1/2 accumulators
    __shared__ float sDen[3][64];

    const int t = threadIdx.x;
    const int lane = t & 31, wid = t >> 5;
    const int wg = wid >> 3;                // 0,1,2 (chunk-range group)
    const int w8 = wid & 7;
    const int mw = w8 >> 2, nw = w8 & 3;
    const int lr = lane >> 2, lc = lane & 3;
    const int i0 = blockIdx.x * 64;
    const bool do_den = (w8 == 1) || (w8 == 6);
    const int q0 = (wg == 0) ? 0 : (wg == 1) ? 171 : 342;
    const int q1 = (wg == 0) ? 171 : (wg == 1) ? 342 : 512;

    // stage E2/F2 tables
    {
        const float4* e4 = reinterpret_cast<const float4*>(g_E2);
        const float4* f4 = reinterpret_cast<const float4*>(g_F2);
        float4* s4 = reinterpret_cast<float4*>(sEF);
        for (int k = t; k < N / 4; k += 768) {
            s4[k]         = e4[k];
            s4[N / 4 + k] = f4[k];
        }
    }
    __syncthreads();

    const float4* sE4 = reinterpret_cast<const float4*>(sEF);
    const float4* sF4 = reinterpret_cast<const float4*>(sEF + N);

    // single base pointers + immediate offsets (reg diet)
    const int4* ar = reinterpret_cast<const int4*>(adj) +
                     (size_t)(i0 + mw * 32 + lr) * (N / 4) + lc;
    const uint2* bb = g_hTb + ((nw * 4) * 4 + lc) * 8 + lr;

    float e1[4], f1[4];
    #pragma unroll
    for (int k = 0; k < 4; ++k) {
        const int row = i0 + mw * 32 + lr + 8 * k;
        e1[k] = g_E1[row];
        f1[k] = g_F1[row];
    }

    float acc[2][4][4];
    #pragma unroll
    for (int mt = 0; mt < 2; ++mt)
        #pragma unroll
        for (int nt = 0; nt < 4; ++nt)
            #pragma unroll
            for (int r = 0; r < 4; ++r) acc[mt][nt][r] = 0.f;
    float dpT[4] = {0.f, 0.f, 0.f, 0.f};

    // initial loads for chunk q0
    int4 a4[4];
    uint2 b2[4];
    #pragma unroll
    for (int k = 0; k < 4; ++k) a4[k] = __ldg(ar + q0 * 4 + k * (8 * (N / 4)));
    #pragma unroll
    for (int nt = 0; nt < 4; ++nt) b2[nt] = __ldg(bb + q0 * 512 + nt * 32);

    #pragma unroll 1
    for (int q = q0; q < q1; ++q) {
        const float4 e4 = sE4[q * 4 + lc];
        const float4 f4 = sF4[q * 4 + lc];

        float w[4][4];
        #pragma unroll
        for (int k = 0; k < 4; ++k) {
            const float ek = e1[k], fk = f1[k];
            w[k][0] = a4[k].x ? fmaxf(ek * e4.x, fk * f4.x) : 0.f;
            w[k][1] = a4[k].y ? fmaxf(ek * e4.y, fk * f4.y) : 0.f;
            w[k][2] = a4[k].z ? fmaxf(ek * e4.z, fk * f4.z) : 0.f;
            w[k][3] = a4[k].w ? fmaxf(ek * e4.w, fk * f4.w) : 0.f;
        }
        if (do_den) {
            #pragma unroll
            for (int k = 0; k < 4; ++k)
                dpT[k] += (w[k][0] + w[k][1]) + (w[k][2] + w[k][3]);
        }
        // a4 dead -> prefetch next chunk's adj
        if (q + 1 < q1) {
            #pragma unroll
            for (int k = 0; k < 4; ++k) a4[k] = __ldg(ar + (q + 1) * 4 + k * (8 * (N / 4)));
        }
        #pragma unroll
        for (int mt = 0; mt < 2; ++mt) {
            const uint32_t af0 = pack_h2(w[2 * mt][0],     w[2 * mt][1]);
            const uint32_t af1 = pack_h2(w[2 * mt + 1][0], w[2 * mt + 1][1]);
            const uint32_t af2 = pack_h2(w[2 * mt][2],     w[2 * mt][3]);
            const uint32_t af3 = pack_h2(w[2 * mt + 1][2], w[2 * mt + 1][3]);
            #pragma unroll
            for (int nt = 0; nt < 4; ++nt)
                mma16(acc[mt][nt], af0, af1, af2, af3, b2[nt].x, b2[nt].y);
        }
        // b2 consumed at issue -> prefetch next chunk's B fragments
        if (q + 1 < q1) {
            #pragma unroll
            for (int nt = 0; nt < 4; ++nt) b2[nt] = __ldg(bb + (q + 1) * 512 + nt * 32);
        }
    }

    // per-group denominators
    if (do_den) {
        #pragma unroll
        for (int k = 0; k < 4; ++k) {
            float v = dpT[k];
            v += __shfl_xor_sync(0xffffffffu, v, 1);
            v += __shfl_xor_sync(0xffffffffu, v, 2);
            if (lc == 0) sDen[wg][mw * 32 + 8 * k + lr] = v;
        }
    }

    // groups 1,2 export accumulators
    if (wg > 0) {
        float* mc = sMerge + (t - 256) * 32;   // g1 -> [0,8192), g2 -> [8192,16384)
        #pragma unroll
        for (int mt = 0; mt < 2; ++mt)
            #pragma unroll
            for (int nt = 0; nt < 4; ++nt)
                #pragma unroll
                for (int r = 0; r < 4; ++r)
                    mc[mt * 16 + nt * 4 + r] = acc[mt][nt][r];
    }
    __syncthreads();

    // group 0 merges, normalizes, stores
    if (wg == 0) {
        const float* mc1 = sMerge + t * 32;
        const float* mc2 = sMerge + 8192 + t * 32;
        #pragma unroll
        for (int mt = 0; mt < 2; ++mt)
            #pragma unroll
            for (int nt = 0; nt < 4; ++nt)
                #pragma unroll
                for (int r = 0; r < 4; ++r)
                    acc[mt][nt][r] += mc1[mt * 16 + nt * 4 + r] + mc2[mt * 16 + nt * 4 + r];

        #pragma unroll
        for (int mt = 0; mt < 2; ++mt) {
            const int r0 = mw * 32 + mt * 16 + lr;
            const float inv0 = 1.f / (sDen[0][r0]     + sDen[1][r0]     + sDen[2][r0]);
            const float inv1 = 1.f / (sDen[0][r0 + 8] + sDen[1][r0 + 8] + sDen[2][r0 + 8]);
            #pragma unroll
            for (int nt = 0; nt < 4; ++nt) {
                const int col = nw * 32 + nt * 8 + lc * 2;
                float2 v0, v1;
                v0.x = elu_f(acc[mt][nt][0] * inv0);
                v0.y = elu_f(acc[mt][nt][1] * inv0);
                v1.x = elu_f(acc[mt][nt][2] * inv1);
                v1.y = elu_f(acc[mt][nt][3] * inv1);
                *reinterpret_cast<float2*>(out + (size_t)(i0 + r0) * FOUT + col)     = v0;
                *reinterpret_cast<float2*>(out + (size_t)(i0 + r0 + 8) * FOUT + col) = v1;
            }
        }
    }
}

// ---------------------------------------------------------------------------
extern "C" void kernel_launch(void* const* d_in, const int* in_sizes, int n_in,
                              void* d_out, int out_size) {
    const float* X   = (const float*)d_in[0];   // 8192 x 512
    const int*   adj = (const int*)  d_in[1];   // 8192 x 8192
    const float* W   = (const float*)d_in[2];   // 512 x 128
    const float* a   = (const float*)d_in[3];   // 256 x 1
    float*       out = (float*)d_out;           // 8192 x 128

    cudaFuncSetAttribute(k_agg, cudaFuncAttributeMaxDynamicSharedMemorySize, 131072);

    k_gemm_hw<<<N / 64, 512>>>(X, W);
    k_scores<<<N, 128>>>(a);
    k_agg<<<N / 64, 768, 131072>>>(adj, out);
}

// round 14
// speedup vs baseline: 1.4398x; 1.4398x over previous
#include <cuda_runtime.h>
#include <cuda_fp16.h>
#include <cstdint>
#include <math.h>

typedef unsigned long long ull;

#define FMA2(acc, a, b) asm("fma.rn.f32x2 %0, %1, %2, %0;" : "+l"(acc) : "l"(a), "l"(b))
#define PACK2(d, s)     asm("mov.b64 %0, {%1, %1};" : "=l"(d) : "f"(s))
#define UNPACK2(lo, hi, s) asm("mov.b64 {%0, %1}, %2;" : "=f"(lo), "=f"(hi) : "l"(s))

constexpr int N    = 8192;
constexpr int FIN  = 512;
constexpr int FOUT = 128;
constexpr int NQ   = 512;    // k16 chunks; group0: [0,256), group1: [256,512)

__device__ float g_h[N * FOUT];
__device__ uint2 g_hTb[NQ * 16 * 4 * 8];     // fp16 B fragments of h^T (2MB, L2-resident)
__device__ float g_E1[N], g_F1[N], g_E2[N], g_F2[N];

__device__ __forceinline__ uint32_t pack_h2(float lo, float hi) {
    uint32_t r;
    asm("cvt.rn.f16x2.f32 %0, %1, %2;" : "=r"(r) : "f"(hi), "f"(lo));
    return r;
}
__device__ __forceinline__ float2 h2f2(uint32_t u) {
    __half2 h = *reinterpret_cast<const __half2*>(&u);
    return __half22float2(h);
}

// m16n8k16 fp16 warp MMA, fp32 accumulate
__device__ __forceinline__ void mma16(float* c, uint32_t a0, uint32_t a1, uint32_t a2,
                                      uint32_t a3, uint32_t b0, uint32_t b1) {
    asm volatile(
        "mma.sync.aligned.m16n8k16.row.col.f32.f16.f16.f32 "
        "{%0,%1,%2,%3}, {%4,%5,%6,%7}, {%8,%9}, {%0,%1,%2,%3};"
        : "+f"(c[0]), "+f"(c[1]), "+f"(c[2]), "+f"(c[3])
        : "r"(a0), "r"(a1), "r"(a2), "r"(a3), "r"(b0), "r"(b1));
}

__device__ __forceinline__ float elu_f(float v) { return v > 0.f ? v : expm1f(v); }

// ---------------------------------------------------------------------------
// Kernel A: h = X @ W (fp32 FFMA2), BM=64, 512 threads (2 col-halves of 64).
// Emits g_h and fp16 B-fragment hT.  (R13 version: 45us)
// ---------------------------------------------------------------------------
__global__ void __launch_bounds__(512) k_gemm_hw(const float* __restrict__ X,
                                                 const float* __restrict__ W) {
    __shared__ float sX[64][32];    // 8KB
    __shared__ float sB[32][FOUT];  // 16KB
    const int t = threadIdx.x;
    const int g  = t >> 8;          // col half: cols [64g, 64g+64)
    const int u  = t & 255;
    const int tx = u & 15;          // 4 cols: c0 = 64g + 4tx
    const int ty = u >> 4;          // rows ty + 16k, k<4
    const int m0 = blockIdx.x * 64;
    const int xr = t >> 3, xc0 = (t & 7) * 4;
    const int wr = t >> 4, wc0 = (t & 15) * 8;

    ull acc[4][2] = {};
    for (int kc = 0; kc < FIN / 32; ++kc) {
        const int k0 = kc * 32;
        __syncthreads();
        {
            float4*       dx = reinterpret_cast<float4*>(&sX[xr][xc0]);
            const float4* sx = reinterpret_cast<const float4*>(X + (size_t)(m0 + xr) * FIN + k0 + xc0);
            dx[0] = sx[0];
            float4*       dw = reinterpret_cast<float4*>(&sB[wr][wc0]);
            const float4* sw = reinterpret_cast<const float4*>(W + (size_t)(k0 + wr) * FOUT + wc0);
            dw[0] = sw[0]; dw[1] = sw[1];
        }
        __syncthreads();
        #pragma unroll 8
        for (int kk = 0; kk < 32; ++kk) {
            ulonglong2 b2 = *reinterpret_cast<const ulonglong2*>(&sB[kk][g * 64 + tx * 4]);
            #pragma unroll
            for (int k = 0; k < 4; ++k) {
                ull ap; PACK2(ap, sX[ty + 16 * k][kk]);
                FMA2(acc[k][0], ap, b2.x);
                FMA2(acc[k][1], ap, b2.y);
            }
        }
    }
    __half* hTb = reinterpret_cast<__half*>(g_hTb);
    #pragma unroll
    for (int k = 0; k < 4; ++k) {
        const int r = m0 + ty + 16 * k;
        float4 o;
        UNPACK2(o.x, o.y, acc[k][0]);
        UNPACK2(o.z, o.w, acc[k][1]);
        reinterpret_cast<float4*>(g_h + (size_t)r * FOUT)[g * 16 + tx] = o;
        const int q   = r >> 4;
        const int lcr = (r >> 2) & 3;
        const int p   = r & 3;
        const float v[4] = {o.x, o.y, o.z, o.w};
        #pragma unroll
        for (int c = 0; c < 4; ++c) {
            const int f = g * 64 + tx * 4 + c;
            const int idx = (((q * 16 + (f >> 3)) * 4 + lcr) * 8 + (f & 7)) * 4 + p;
            hTb[idx] = __float2half_rn(v[c]);
        }
    }
}

// ---------------------------------------------------------------------------
// Kernel B: E/F exp vectors
// ---------------------------------------------------------------------------
__global__ void __launch_bounds__(128) k_scores(const float* __restrict__ a) {
    const int i = blockIdx.x;
    const int t = threadIdx.x;
    const float hv = g_h[(size_t)i * FOUT + t];
    float p1 = hv * __ldg(&a[t]);
    float p2 = hv * __ldg(&a[FOUT + t]);
    #pragma unroll
    for (int off = 16; off; off >>= 1) {
        p1 += __shfl_xor_sync(0xffffffffu, p1, off);
        p2 += __shfl_xor_sync(0xffffffffu, p2, off);
    }
    __shared__ float r1[4], r2[4];
    const int w = t >> 5;
    if ((t & 31) == 0) { r1[w] = p1; r2[w] = p2; }
    __syncthreads();
    if (t == 0) {
        const float s1 = r1[0] + r1[1] + r1[2] + r1[3];
        const float s2 = r2[0] + r2[1] + r2[2] + r2[3];
        g_E1[i] = __expf(s1);  g_F1[i] = __expf(0.2f * s1);
        g_E2[i] = __expf(s2);  g_F2[i] = __expf(0.2f * s2);
    }
}

// ---------------------------------------------------------------------------
// Kernel C (exact R12 config, 190us): fp16 warp-MMA aggregation, 16 warps
// (512 thr), j-split in CTA. wid 0-7: chunks [0,256); wid 8-15: [256,512).
// 4 warps/SMSP x 8 independent HMMAs in flight. No mainloop syncs; merge
// group-1 accumulators + dens via smem. den from ROUNDED fp16 fragments on
// wid 1,6,9,14 -> exact softmax cancel.
// ---------------------------------------------------------------------------
__global__ void __launch_bounds__(512, 1) k_agg(const int* __restrict__ adj,
                                                float* __restrict__ out) {
    extern __shared__ float smem[];
    float* sEF    = smem;                   // 16384 f (64KB): E2 | F2
    float* sMerge = smem + 2 * N;           // 8192 f (32KB): group-1 accumulators
    __shared__ float sDen0[64], sDen1[64];

    const int t = threadIdx.x;
    const int lane = t & 31, wid = t >> 5;
    const int wg = wid >> 3;                // 0 or 1 (chunk-range group)
    const int w8 = wid & 7;
    const int mw = w8 >> 2, nw = w8 & 3;
    const int lr = lane >> 2, lc = lane & 3;
    const int i0 = blockIdx.x * 64;
    const bool do_den = (w8 == 1) || (w8 == 6);   // wid 1,6 (g0); 9,14 (g1)
    const int q0 = wg * 256, q1 = q0 + 256;

    // stage E2/F2 tables
    {
        const float4* e4 = reinterpret_cast<const float4*>(g_E2);
        const float4* f4 = reinterpret_cast<const float4*>(g_F2);
        float4* s4 = reinterpret_cast<float4*>(sEF);
        for (int k = t; k < N / 4; k += 512) {
            s4[k]         = e4[k];
            s4[N / 4 + k] = f4[k];
        }
    }
    __syncthreads();

    const float4* sE4 = reinterpret_cast<const float4*>(sEF);
    const float4* sF4 = reinterpret_cast<const float4*>(sEF + N);
    const int4* adj4 = reinterpret_cast<const int4*>(adj);

    float e1[4], f1[4];
    const int4* arow[4];
    #pragma unroll
    for (int k = 0; k < 4; ++k) {
        const int row = i0 + mw * 32 + lr + 8 * k;
        e1[k] = g_E1[row];
        f1[k] = g_F1[row];
        arow[k] = adj4 + (size_t)row * (N / 4) + lc;
    }

    // depth-1 register prefetch
    int4 a4n[4];
    uint2 b2n[4];
    #pragma unroll
    for (int k = 0; k < 4; ++k) a4n[k] = __ldg(arow[k] + q0 * 4);
    #pragma unroll
    for (int nt = 0; nt < 4; ++nt)
        b2n[nt] = __ldg(&g_hTb[((q0 * 16 + nw * 4 + nt) * 4 + lc) * 8 + lr]);

    float acc[2][4][4];
    #pragma unroll
    for (int mt = 0; mt < 2; ++mt)
        #pragma unroll
        for (int nt = 0; nt < 4; ++nt)
            #pragma unroll
            for (int r = 0; r < 4; ++r) acc[mt][nt][r] = 0.f;
    float dpT[4] = {0.f, 0.f, 0.f, 0.f};

    #pragma unroll 1
    for (int q = q0; q < q1; ++q) {
        int4 a4[4];
        uint2 b2[4];
        #pragma unroll
        for (int k = 0; k < 4; ++k) a4[k] = a4n[k];
        #pragma unroll
        for (int nt = 0; nt < 4; ++nt) b2[nt] = b2n[nt];
        if (q + 1 < q1) {
            #pragma unroll
            for (int k = 0; k < 4; ++k) a4n[k] = __ldg(arow[k] + (q + 1) * 4);
            #pragma unroll
            for (int nt = 0; nt < 4; ++nt)
                b2n[nt] = __ldg(&g_hTb[(((q + 1) * 16 + nw * 4 + nt) * 4 + lc) * 8 + lr]);
        }
        const float4 e4 = sE4[q * 4 + lc];
        const float4 f4 = sF4[q * 4 + lc];

        float w[4][4];
        #pragma unroll
        for (int k = 0; k < 4; ++k) {
            const float ek = e1[k], fk = f1[k];
            w[k][0] = a4[k].x ? fmaxf(ek * e4.x, fk * f4.x) : 0.f;
            w[k][1] = a4[k].y ? fmaxf(ek * e4.y, fk * f4.y) : 0.f;
            w[k][2] = a4[k].z ? fmaxf(ek * e4.z, fk * f4.z) : 0.f;
            w[k][3] = a4[k].w ? fmaxf(ek * e4.w, fk * f4.w) : 0.f;
        }
        #pragma unroll
        for (int mt = 0; mt < 2; ++mt) {
            const uint32_t af0 = pack_h2(w[2 * mt][0],     w[2 * mt][1]);
            const uint32_t af1 = pack_h2(w[2 * mt + 1][0], w[2 * mt + 1][1]);
            const uint32_t af2 = pack_h2(w[2 * mt][2],     w[2 * mt][3]);
            const uint32_t af3 = pack_h2(w[2 * mt + 1][2], w[2 * mt + 1][3]);
            #pragma unroll
            for (int nt = 0; nt < 4; ++nt)
                mma16(acc[mt][nt], af0, af1, af2, af3, b2[nt].x, b2[nt].y);
            if (do_den) {   // den from ROUNDED fragments -> exact cancel
                const float2 d0 = h2f2(af0), d1 = h2f2(af1);
                const float2 d2 = h2f2(af2), d3 = h2f2(af3);
                dpT[2 * mt]     += (d0.x + d0.y) + (d2.x + d2.y);
                dpT[2 * mt + 1] += (d1.x + d1.y) + (d3.x + d3.y);
            }
        }
    }

    // per-group denominators
    if (do_den) {
        #pragma unroll
        for (int k = 0; k < 4; ++k) {
            float v = dpT[k];
            v += __shfl_xor_sync(0xffffffffu, v, 1);
            v += __shfl_xor_sync(0xffffffffu, v, 2);
            if (lc == 0) {
                if (wg == 0) sDen0[mw * 32 + 8 * k + lr] = v;
                else         sDen1[mw * 32 + 8 * k + lr] = v;
            }
        }
    }

    // group 1 exports accumulators
    if (wg == 1) {
        const int u = t - 256;
        float* mc = sMerge + u * 32;
        #pragma unroll
        for (int mt = 0; mt < 2; ++mt)
            #pragma unroll
            for (int nt = 0; nt < 4; ++nt)
                #pragma unroll
                for (int r = 0; r < 4; ++r)
                    mc[mt * 16 + nt * 4 + r] = acc[mt][nt][r];
    }
    __syncthreads();

    // group 0 merges, normalizes, stores
    if (wg == 0) {
        const float* mc = sMerge + t * 32;
        #pragma unroll
        for (int mt = 0; mt < 2; ++mt)
            #pragma unroll
            for (int nt = 0; nt < 4; ++nt)
                #pragma unroll
                for (int r = 0; r < 4; ++r)
                    acc[mt][nt][r] += mc[mt * 16 + nt * 4 + r];

        #pragma unroll
        for (int mt = 0; mt < 2; ++mt) {
            const int r0 = mw * 32 + mt * 16 + lr;
            const float inv0 = 1.f / (sDen0[r0]     + sDen1[r0]);
            const float inv1 = 1.f / (sDen0[r0 + 8] + sDen1[r0 + 8]);
            #pragma unroll
            for (int nt = 0; nt < 4; ++nt) {
                const int col = nw * 32 + nt * 8 + lc * 2;
                float2 v0, v1;
                v0.x = elu_f(acc[mt][nt][0] * inv0);
                v0.y = elu_f(acc[mt][nt][1] * inv0);
                v1.x = elu_f(acc[mt][nt][2] * inv1);
                v1.y = elu_f(acc[mt][nt][3] * inv1);
                *reinterpret_cast<float2*>(out + (size_t)(i0 + r0) * FOUT + col)     = v0;
                *reinterpret_cast<float2*>(out + (size_t)(i0 + r0 + 8) * FOUT + col) = v1;
            }
        }
    }
}

// ---------------------------------------------------------------------------
extern "C" void kernel_launch(void* const* d_in, const int* in_sizes, int n_in,
                              void* d_out, int out_size) {
    const float* X   = (const float*)d_in[0];   // 8192 x 512
    const int*   adj = (const int*)  d_in[1];   // 8192 x 8192
    const float* W   = (const float*)d_in[2];   // 512 x 128
    const float* a   = (const float*)d_in[3];   // 256 x 1
    float*       out = (float*)d_out;           // 8192 x 128

    cudaFuncSetAttribute(k_agg, cudaFuncAttributeMaxDynamicSharedMemorySize, 98304);

    k_gemm_hw<<<N / 64, 512>>>(X, W);
    k_scores<<<N, 128>>>(a);
    k_agg<<<N / 64, 512, 98304>>>(adj, out);
}